// round 15
// baseline (speedup 1.0000x reference)
#include <cuda_runtime.h>
#include <cuda_bf16.h>
#include <cuda_fp8.h>
#include <cstdint>

// Shapes fixed by dataset
#define MDIM 16384
#define NDIM 4096
#define KDIM 4096

__device__ uint8_t g_qx[(size_t)MDIM * KDIM];   // 64 MiB
__device__ uint8_t g_qw[(size_t)NDIM * KDIM];   // 16 MiB
__device__ unsigned int g_amax_bits;

static __device__ __forceinline__ uint32_t smem_u32(const void* p) {
    return (uint32_t)__cvta_generic_to_shared(p);
}

// ---------------------------------------------------------------------------
// 1) amax reduction (4-way unrolled grid-stride for MLP)
// ---------------------------------------------------------------------------
__global__ void init_amax_kernel() { g_amax_bits = 0u; }

__global__ void amax_kernel(const float* __restrict__ x, int n4) {
    const float4* x4 = (const float4*)x;
    const int g = gridDim.x * blockDim.x;
    float m = 0.0f;
    int i = blockIdx.x * blockDim.x + threadIdx.x;
    for (; i + 3 * g < n4; i += 4 * g) {
        float4 a = __ldcs(&x4[i]);
        float4 b = __ldcs(&x4[i + g]);
        float4 c = __ldcs(&x4[i + 2 * g]);
        float4 d = __ldcs(&x4[i + 3 * g]);
        m = fmaxf(m, fmaxf(fmaxf(fabsf(a.x), fabsf(a.y)), fmaxf(fabsf(a.z), fabsf(a.w))));
        m = fmaxf(m, fmaxf(fmaxf(fabsf(b.x), fabsf(b.y)), fmaxf(fabsf(b.z), fabsf(b.w))));
        m = fmaxf(m, fmaxf(fmaxf(fabsf(c.x), fabsf(c.y)), fmaxf(fabsf(c.z), fabsf(c.w))));
        m = fmaxf(m, fmaxf(fmaxf(fabsf(d.x), fabsf(d.y)), fmaxf(fabsf(d.z), fabsf(d.w))));
    }
    for (; i < n4; i += g) {
        float4 a = __ldcs(&x4[i]);
        m = fmaxf(m, fmaxf(fmaxf(fabsf(a.x), fabsf(a.y)), fmaxf(fabsf(a.z), fabsf(a.w))));
    }
#pragma unroll
    for (int o = 16; o > 0; o >>= 1)
        m = fmaxf(m, __shfl_xor_sync(0xffffffffu, m, o));
    if ((threadIdx.x & 31) == 0)
        atomicMax(&g_amax_bits, __float_as_uint(m)); // m >= 0
}

// ---------------------------------------------------------------------------
// 2) one pass: quantize x -> e4m3 bytes AND convert w -> e4m3 bytes
// ---------------------------------------------------------------------------
static __device__ __forceinline__ uchar4 q4s(float4 v, float s) {
    uchar4 o;
    o.x = __nv_fp8_e4m3(v.x * s).__x;
    o.y = __nv_fp8_e4m3(v.y * s).__x;
    o.z = __nv_fp8_e4m3(v.z * s).__x;
    o.w = __nv_fp8_e4m3(v.w * s).__x;
    return o;
}

__global__ void quantize_both_kernel(const float* __restrict__ x,
                                     const float* __restrict__ w,
                                     int nx4, int nw4) {
    float amax = fmaxf(__uint_as_float(g_amax_bits), 1e-12f);
    float s = 448.0f / amax;
    const int g = gridDim.x * blockDim.x;
    const int total = nx4 + nw4;
    int i = blockIdx.x * blockDim.x + threadIdx.x;
    for (; i + g < total; i += 2 * g) {
        int i2 = i + g;
        float4 v0 = (i  < nx4) ? __ldcs(&((const float4*)x)[i])
                               : __ldcs(&((const float4*)w)[i - nx4]);
        float4 v1 = (i2 < nx4) ? __ldcs(&((const float4*)x)[i2])
                               : __ldcs(&((const float4*)w)[i2 - nx4]);
        uchar4 o0 = q4s(v0, (i  < nx4) ? s : 1.0f);
        uchar4 o1 = q4s(v1, (i2 < nx4) ? s : 1.0f);
        if (i  < nx4) ((uchar4*)g_qx)[i]        = o0;
        else          ((uchar4*)g_qw)[i  - nx4] = o0;
        if (i2 < nx4) ((uchar4*)g_qx)[i2]       = o1;
        else          ((uchar4*)g_qw)[i2 - nx4] = o1;
    }
    for (; i < total; i += g) {
        float4 v = (i < nx4) ? __ldcs(&((const float4*)x)[i])
                             : __ldcs(&((const float4*)w)[i - nx4]);
        uchar4 o = q4s(v, (i < nx4) ? s : 1.0f);
        if (i < nx4) ((uchar4*)g_qx)[i]       = o;
        else         ((uchar4*)g_qw)[i - nx4] = o;
    }
}

// ---------------------------------------------------------------------------
// 3) fp8 GEMM via mma.sync m16n8k32 e4m3:
//    128x128 CTA tile, 512 threads, 16 warps (4x4), warp tile 32x32.
//    2 CTAs/SM -> 8 warps/SMSP (occupancy-doubled vs 256-thread variant).
//    BK=64 bytes/chunk, 4-stage cp.async pipeline.
// ---------------------------------------------------------------------------
#define BM 128
#define BN 128
#define BKB 64                  // K bytes per chunk (= k64 in fp8)
#define STAGES 4
#define RSTR 80                 // padded smem row stride (16B aligned)
#define A_STAGE (BM * RSTR)     // 10240
#define B_STAGE (BN * RSTR)     // 10240
#define STAGE_BYTES (A_STAGE + B_STAGE)   // 20480
#define SMEM_TOTAL (STAGES * STAGE_BYTES) // 81920 (x2 CTAs = 160KB <= 228KB)
#define ROWSKIP ((size_t)64 * KDIM)

static __device__ __forceinline__ void cp16(uint32_t dst, const void* src) {
    asm volatile("cp.async.cg.shared.global [%0], [%1], 16;"
                 :: "r"(dst), "l"(src) : "memory");
}

static __device__ __forceinline__ void ldsm4(uint32_t addr, uint32_t& r0,
                                             uint32_t& r1, uint32_t& r2,
                                             uint32_t& r3) {
    asm volatile("ldmatrix.sync.aligned.m8n8.x4.shared.b16 {%0,%1,%2,%3}, [%4];"
                 : "=r"(r0), "=r"(r1), "=r"(r2), "=r"(r3) : "r"(addr));
}

__global__ __launch_bounds__(512, 2)
void gemm_kernel(const float* __restrict__ bias,
                 const float* __restrict__ w_scale,
                 float* __restrict__ C) {
    extern __shared__ char smem[];
    const uint32_t sbase = smem_u32(smem);
    const int tid  = threadIdx.x;
    const int warp = tid >> 5;
    const int lane = tid & 31;
    const int wm   = warp >> 2;   // 0..3: 32-row warp tile
    const int wn   = warp & 3;    // 0..3: 32-col warp tile
    const int bm   = blockIdx.y * BM;
    const int bn   = blockIdx.x * BN;
    const int NCHUNK = KDIM / BKB;   // 64

    // ---- global source cursors: 1 vec16 per tile per thread ----
    const int lrow = tid >> 2;            // 0..127
    const int lc16 = (tid & 3) * 16;      // 0..48
    const uint8_t* pa = g_qx + (size_t)(bm + lrow) * KDIM + lc16;
    const uint8_t* pb = g_qw + (size_t)(bn + lrow) * KDIM + lc16;

    // ---- smem store bases (stage 0; stage adds const) ----
    const uint32_t ast = sbase + lrow * RSTR + lc16;
    const uint32_t bst = ast + A_STAGE;

    // ---- fragment base addresses (stage 0, kstep 0, subtile 0) ----
    // A: rows wm*32 + mt*16 + (lane&15), col (lane>>4)*16 ; mt offset = imm
    const uint32_t afb = sbase + (wm * 32 + (lane & 15)) * RSTR
                       + (lane >> 4) * 16;
    // B: rows wn*32 + p*16 + ((lane>>4)<<3)+(lane&7), col ((lane>>3)&1)*16
    const uint32_t bfb = sbase + A_STAGE
                       + (wn * 32 + ((lane >> 4) << 3) + (lane & 7)) * RSTR
                       + ((lane >> 3) & 1) * 16;

    float acc[2][4][4];
#pragma unroll
    for (int a = 0; a < 2; a++)
#pragma unroll
        for (int b = 0; b < 4; b++)
#pragma unroll
            for (int c = 0; c < 4; c++) acc[a][b][c] = 0.0f;

    // prologue: fill stages 0..2 (one cp16 per tile per thread per stage)
#pragma unroll
    for (int s = 0; s < STAGES - 1; s++) {
        cp16(ast + s * STAGE_BYTES, pa + s * BKB);
        cp16(bst + s * STAGE_BYTES, pb + s * BKB);
        asm volatile("cp.async.commit_group;" ::: "memory");
    }

    pa += (STAGES - 1) * BKB;
    pb += (STAGES - 1) * BKB;
    int kpref = (STAGES - 1) * BKB;

#pragma unroll 1
    for (int it = 0; it < NCHUNK; it += STAGES) {
#pragma unroll
        for (int s = 0; s < STAGES; s++) {    // s is compile-time
            asm volatile("cp.async.wait_group %0;" :: "n"(STAGES - 2) : "memory");
            __syncthreads();

            uint32_t af[2][4];
            uint32_t bf[4][2];
            // kstep 0 fragments (LDSM latency hides under cp.async issue below)
#pragma unroll
            for (int mt = 0; mt < 2; mt++)
                ldsm4(afb + s * STAGE_BYTES + mt * (16 * RSTR),
                      af[mt][0], af[mt][1], af[mt][2], af[mt][3]);
#pragma unroll
            for (int p = 0; p < 2; p++)
                ldsm4(bfb + s * STAGE_BYTES + p * (16 * RSTR),
                      bf[2 * p][0], bf[2 * p][1], bf[2 * p + 1][0], bf[2 * p + 1][1]);

            // prefetch into the stage just freed
            if (kpref < KDIM) {
                const int ps = (s + STAGES - 1) % STAGES;   // compile-time
                cp16(ast + ps * STAGE_BYTES, pa);
                cp16(bst + ps * STAGE_BYTES, pb);
            }
            pa += BKB; pb += BKB; kpref += BKB;
            asm volatile("cp.async.commit_group;" ::: "memory");

#pragma unroll
            for (int mt = 0; mt < 2; mt++)
#pragma unroll
                for (int nt = 0; nt < 4; nt++)
                    asm("mma.sync.aligned.m16n8k32.row.col.f32.e4m3.e4m3.f32 "
                        "{%0,%1,%2,%3}, {%4,%5,%6,%7}, {%8,%9}, {%0,%1,%2,%3};"
                        : "+f"(acc[mt][nt][0]), "+f"(acc[mt][nt][1]),
                          "+f"(acc[mt][nt][2]), "+f"(acc[mt][nt][3])
                        : "r"(af[mt][0]), "r"(af[mt][1]),
                          "r"(af[mt][2]), "r"(af[mt][3]),
                          "r"(bf[nt][0]), "r"(bf[nt][1]));

            // kstep 1 (byte offset 32 within chunk row)
#pragma unroll
            for (int mt = 0; mt < 2; mt++)
                ldsm4(afb + s * STAGE_BYTES + mt * (16 * RSTR) + 32,
                      af[mt][0], af[mt][1], af[mt][2], af[mt][3]);
#pragma unroll
            for (int p = 0; p < 2; p++)
                ldsm4(bfb + s * STAGE_BYTES + p * (16 * RSTR) + 32,
                      bf[2 * p][0], bf[2 * p][1], bf[2 * p + 1][0], bf[2 * p + 1][1]);
#pragma unroll
            for (int mt = 0; mt < 2; mt++)
#pragma unroll
                for (int nt = 0; nt < 4; nt++)
                    asm("mma.sync.aligned.m16n8k32.row.col.f32.e4m3.e4m3.f32 "
                        "{%0,%1,%2,%3}, {%4,%5,%6,%7}, {%8,%9}, {%0,%1,%2,%3};"
                        : "+f"(acc[mt][nt][0]), "+f"(acc[mt][nt][1]),
                          "+f"(acc[mt][nt][2]), "+f"(acc[mt][nt][3])
                        : "r"(af[mt][0]), "r"(af[mt][1]),
                          "r"(af[mt][2]), "r"(af[mt][3]),
                          "r"(bf[nt][0]), "r"(bf[nt][1]));
        }
    }

    // epilogue: out = acc * (x_scale * w_scale) + bias
    float amax = fmaxf(__uint_as_float(g_amax_bits), 1e-12f);
    float sq = 448.0f / amax;
    float total = (1.0f / sq) * __ldg(w_scale);

#pragma unroll
    for (int mt = 0; mt < 2; mt++) {
        int r0 = bm + wm * 32 + mt * 16 + (lane >> 2);
#pragma unroll
        for (int nt = 0; nt < 4; nt++) {
            int cix = bn + wn * 32 + nt * 8 + (lane & 3) * 2;
            float b0 = __ldg(&bias[cix]);
            float b1 = __ldg(&bias[cix + 1]);
            float2 v0, v1;
            v0.x = acc[mt][nt][0] * total + b0;
            v0.y = acc[mt][nt][1] * total + b1;
            v1.x = acc[mt][nt][2] * total + b0;
            v1.y = acc[mt][nt][3] * total + b1;
            *(float2*)(C + (size_t)r0 * NDIM + cix)       = v0;
            *(float2*)(C + (size_t)(r0 + 8) * NDIM + cix) = v1;
        }
    }
}

// ---------------------------------------------------------------------------
extern "C" void kernel_launch(void* const* d_in, const int* in_sizes, int n_in,
                              void* d_out, int out_size) {
    const float* x       = (const float*)d_in[0];
    const float* w       = (const float*)d_in[1];
    const float* w_scale = (const float*)d_in[2];
    const float* bias    = (const float*)d_in[3];
    float* out           = (float*)d_out;

    int nx4 = (MDIM * KDIM) / 4;
    int nw4 = (NDIM * KDIM) / 4;

    cudaFuncSetAttribute(gemm_kernel,
                         cudaFuncAttributeMaxDynamicSharedMemorySize, SMEM_TOTAL);

    init_amax_kernel<<<1, 1>>>();
    amax_kernel<<<1184, 256>>>(x, nx4);                  // 8 x 148
    quantize_both_kernel<<<2368, 256>>>(x, w, nx4, nw4); // 16 x 148

    dim3 grid(NDIM / BN, MDIM / BM);
    gemm_kernel<<<grid, 512, SMEM_TOTAL>>>(bias, w_scale, out);
}

// round 16
// speedup vs baseline: 1.5466x; 1.5466x over previous
#include <cuda_runtime.h>
#include <cuda_bf16.h>
#include <cuda_fp8.h>
#include <cstdint>

// Shapes fixed by dataset: M=16384, K=4096, N=4096
__device__ uint8_t g_qx[67108864];   // 16384*4096 bytes
__device__ uint8_t g_qw[16777216];   // 4096*4096 bytes
__device__ unsigned int g_amax_bits;

static __device__ __forceinline__ uint32_t smem_u32(const void* p) {
    return (uint32_t)__cvta_generic_to_shared(p);
}

// ---------------------------------------------------------------------------
// 1) amax reduction (4-way unrolled grid-stride for MLP)
// ---------------------------------------------------------------------------
__global__ void init_amax_kernel() { g_amax_bits = 0u; }

__global__ void amax_kernel(const float* __restrict__ x, int n4) {
    const float4* x4 = (const float4*)x;
    const int g = gridDim.x * blockDim.x;
    float m = 0.0f;
    int i = blockIdx.x * blockDim.x + threadIdx.x;
    for (; i + 3 * g < n4; i += 4 * g) {
        float4 a = __ldcs(&x4[i]);
        float4 b = __ldcs(&x4[i + g]);
        float4 c = __ldcs(&x4[i + 2 * g]);
        float4 d = __ldcs(&x4[i + 3 * g]);
        m = fmaxf(m, fmaxf(fmaxf(fabsf(a.x), fabsf(a.y)), fmaxf(fabsf(a.z), fabsf(a.w))));
        m = fmaxf(m, fmaxf(fmaxf(fabsf(b.x), fabsf(b.y)), fmaxf(fabsf(b.z), fabsf(b.w))));
        m = fmaxf(m, fmaxf(fmaxf(fabsf(c.x), fabsf(c.y)), fmaxf(fabsf(c.z), fabsf(c.w))));
        m = fmaxf(m, fmaxf(fmaxf(fabsf(d.x), fabsf(d.y)), fmaxf(fabsf(d.z), fabsf(d.w))));
    }
    for (; i < n4; i += g) {
        float4 a = __ldcs(&x4[i]);
        m = fmaxf(m, fmaxf(fmaxf(fabsf(a.x), fabsf(a.y)), fmaxf(fabsf(a.z), fabsf(a.w))));
    }
#pragma unroll
    for (int o = 16; o > 0; o >>= 1)
        m = fmaxf(m, __shfl_xor_sync(0xffffffffu, m, o));
    if ((threadIdx.x & 31) == 0)
        atomicMax(&g_amax_bits, __float_as_uint(m)); // m >= 0
}

// ---------------------------------------------------------------------------
// 2) one pass: quantize x -> e4m3 bytes AND convert w -> e4m3 bytes
// ---------------------------------------------------------------------------
static __device__ __forceinline__ uchar4 q4s(float4 v, float s) {
    uchar4 o;
    o.x = __nv_fp8_e4m3(v.x * s).__x;
    o.y = __nv_fp8_e4m3(v.y * s).__x;
    o.z = __nv_fp8_e4m3(v.z * s).__x;
    o.w = __nv_fp8_e4m3(v.w * s).__x;
    return o;
}

__global__ void quantize_both_kernel(const float* __restrict__ x,
                                     const float* __restrict__ w,
                                     int nx4, int nw4) {
    float amax = fmaxf(__uint_as_float(g_amax_bits), 1e-12f);
    float s = 448.0f / amax;
    const int g = gridDim.x * blockDim.x;
    const int total = nx4 + nw4;
    int i = blockIdx.x * blockDim.x + threadIdx.x;
    for (; i + g < total; i += 2 * g) {
        int i2 = i + g;
        float4 v0 = (i  < nx4) ? __ldcs(&((const float4*)x)[i])
                               : __ldcs(&((const float4*)w)[i - nx4]);
        float4 v1 = (i2 < nx4) ? __ldcs(&((const float4*)x)[i2])
                               : __ldcs(&((const float4*)w)[i2 - nx4]);
        uchar4 o0 = q4s(v0, (i  < nx4) ? s : 1.0f);
        uchar4 o1 = q4s(v1, (i2 < nx4) ? s : 1.0f);
        if (i  < nx4) ((uchar4*)g_qx)[i]        = o0;
        else          ((uchar4*)g_qw)[i  - nx4] = o0;
        if (i2 < nx4) ((uchar4*)g_qx)[i2]       = o1;
        else          ((uchar4*)g_qw)[i2 - nx4] = o1;
    }
    for (; i < total; i += g) {
        float4 v = (i < nx4) ? __ldcs(&((const float4*)x)[i])
                             : __ldcs(&((const float4*)w)[i - nx4]);
        uchar4 o = q4s(v, (i < nx4) ? s : 1.0f);
        if (i < nx4) ((uchar4*)g_qx)[i]       = o;
        else         ((uchar4*)g_qw)[i - nx4] = o;
    }
}

// ---------------------------------------------------------------------------
// 3) fp8 GEMM via mma.sync m16n8k32 e4m3 (champion config):
//    128x128 CTA tile, 8 warps (4x2), warp tile 32x64, 2 CTAs/SM.
//    BK=64 bytes/chunk, 4-stage cp.async pipeline.
//    Loop unrolled by STAGES: all smem addresses are base_reg + const-imm.
// ---------------------------------------------------------------------------
#define BM 128
#define BN 128
#define BKB 64                  // K bytes per chunk (= k64 in fp8)
#define STAGES 4
#define RSTR 80                 // padded smem row stride (16B aligned)
#define A_STAGE (BM * RSTR)     // 10240
#define B_STAGE (BN * RSTR)     // 10240
#define STAGE_BYTES (A_STAGE + B_STAGE)   // 20480
#define SMEM_TOTAL (STAGES * STAGE_BYTES) // 81920 (x2 CTAs <= 228KB)

static __device__ __forceinline__ void cp16(uint32_t dst, const void* src) {
    asm volatile("cp.async.cg.shared.global [%0], [%1], 16;"
                 :: "r"(dst), "l"(src) : "memory");
}

static __device__ __forceinline__ void ldsm_a(uint32_t addr, uint32_t* r) {
    asm volatile("ldmatrix.sync.aligned.m8n8.x4.shared.b16 {%0,%1,%2,%3}, [%4];"
                 : "=r"(r[0]), "=r"(r[1]), "=r"(r[2]), "=r"(r[3]) : "r"(addr));
}

static __device__ __forceinline__ void stg_cs_v2(float* p, float a, float b) {
    asm volatile("st.global.cs.v2.f32 [%0], {%1,%2};"
                 :: "l"(p), "f"(a), "f"(b) : "memory");
}

__global__ __launch_bounds__(256, 2)
void gemm_kernel(const float* __restrict__ bias,
                 const float* __restrict__ w_scale,
                 float* __restrict__ C, int M, int N, int K) {
    extern __shared__ char smem[];
    const uint32_t sbase = smem_u32(smem);
    const int tid  = threadIdx.x;
    const int warp = tid >> 5;
    const int lane = tid & 31;
    const int wm   = warp >> 1;   // 0..3: 32-row warp tile
    const int wn   = warp & 1;    // 0..1: 64-col warp tile
    const int bm   = blockIdx.y * BM;
    const int bn   = blockIdx.x * BN;
    const int NCHUNK = K / BKB;   // 64

    // ---- precomputed global source cursors (2 vec16 per tile per thread) ----
    const int lrow = tid >> 2;            // 0..63
    const int lc16 = (tid & 3) * 16;      // 0..48
    const uint8_t* asrc = g_qx + (size_t)(bm + lrow) * K + lc16;
    const uint8_t* bsrc = g_qw + (size_t)(bn + lrow) * K + lc16;
    const size_t rowskip = (size_t)64 * K;

    // ---- precomputed smem store bases (stage 0; stage adds const) ----
    const uint32_t ast = sbase + lrow * RSTR + lc16;
    const uint32_t bst = ast + A_STAGE;

    // ---- precomputed fragment base addresses (stage 0, kstep 0) ----
    uint32_t afb[2];
#pragma unroll
    for (int mt = 0; mt < 2; mt++)
        afb[mt] = sbase + (wm * 32 + mt * 16 + (lane & 15)) * RSTR
                + (lane >> 4) * 16;
    uint32_t bfb[4];
#pragma unroll
    for (int p = 0; p < 4; p++)
        bfb[p] = sbase + A_STAGE
               + (wn * 64 + p * 16 + ((lane >> 4) << 3) + (lane & 7)) * RSTR
               + ((lane >> 3) & 1) * 16;

    float acc[2][8][4];
#pragma unroll
    for (int a = 0; a < 2; a++)
#pragma unroll
        for (int b = 0; b < 8; b++)
#pragma unroll
            for (int c = 0; c < 4; c++) acc[a][b][c] = 0.0f;

    // prologue: fill stages 0..2
#pragma unroll
    for (int s = 0; s < STAGES - 1; s++) {
        cp16(ast + s * STAGE_BYTES,             asrc + s * BKB);
        cp16(ast + s * STAGE_BYTES + 64 * RSTR, asrc + rowskip + s * BKB);
        cp16(bst + s * STAGE_BYTES,             bsrc + s * BKB);
        cp16(bst + s * STAGE_BYTES + 64 * RSTR, bsrc + rowskip + s * BKB);
        asm volatile("cp.async.commit_group;" ::: "memory");
    }

    int kpref = (STAGES - 1) * BKB;   // byte offset of next chunk to prefetch

#pragma unroll 1
    for (int it = 0; it < NCHUNK; it += STAGES) {
#pragma unroll
        for (int s = 0; s < STAGES; s++) {    // s is compile-time
            asm volatile("cp.async.wait_group %0;" :: "n"(STAGES - 2) : "memory");
            __syncthreads();

            uint32_t af[2][4];
            uint32_t bf[8][2];
            // kstep 0 fragments (LDSM latency hides under cp.async issue below)
#pragma unroll
            for (int mt = 0; mt < 2; mt++)
                ldsm_a(afb[mt] + s * STAGE_BYTES, af[mt]);
#pragma unroll
            for (int p = 0; p < 4; p++) {
                uint32_t r[4];
                ldsm_a(bfb[p] + s * STAGE_BYTES, r);
                bf[2 * p + 0][0] = r[0]; bf[2 * p + 0][1] = r[1];
                bf[2 * p + 1][0] = r[2]; bf[2 * p + 1][1] = r[3];
            }

            // prefetch chunk into the stage just freed (compile-time index)
            if (kpref < K) {
                const int ps = (s + STAGES - 1) % STAGES;   // compile-time
                cp16(ast + ps * STAGE_BYTES,             asrc + kpref);
                cp16(ast + ps * STAGE_BYTES + 64 * RSTR, asrc + rowskip + kpref);
                cp16(bst + ps * STAGE_BYTES,             bsrc + kpref);
                cp16(bst + ps * STAGE_BYTES + 64 * RSTR, bsrc + rowskip + kpref);
            }
            kpref += BKB;
            asm volatile("cp.async.commit_group;" ::: "memory");

#pragma unroll
            for (int mt = 0; mt < 2; mt++)
#pragma unroll
                for (int nt = 0; nt < 8; nt++)
                    asm("mma.sync.aligned.m16n8k32.row.col.f32.e4m3.e4m3.f32 "
                        "{%0,%1,%2,%3}, {%4,%5,%6,%7}, {%8,%9}, {%0,%1,%2,%3};"
                        : "+f"(acc[mt][nt][0]), "+f"(acc[mt][nt][1]),
                          "+f"(acc[mt][nt][2]), "+f"(acc[mt][nt][3])
                        : "r"(af[mt][0]), "r"(af[mt][1]),
                          "r"(af[mt][2]), "r"(af[mt][3]),
                          "r"(bf[nt][0]), "r"(bf[nt][1]));

            // kstep 1 (byte offset 32 within chunk row)
#pragma unroll
            for (int mt = 0; mt < 2; mt++)
                ldsm_a(afb[mt] + s * STAGE_BYTES + 32, af[mt]);
#pragma unroll
            for (int p = 0; p < 4; p++) {
                uint32_t r[4];
                ldsm_a(bfb[p] + s * STAGE_BYTES + 32, r);
                bf[2 * p + 0][0] = r[0]; bf[2 * p + 0][1] = r[1];
                bf[2 * p + 1][0] = r[2]; bf[2 * p + 1][1] = r[3];
            }
#pragma unroll
            for (int mt = 0; mt < 2; mt++)
#pragma unroll
                for (int nt = 0; nt < 8; nt++)
                    asm("mma.sync.aligned.m16n8k32.row.col.f32.e4m3.e4m3.f32 "
                        "{%0,%1,%2,%3}, {%4,%5,%6,%7}, {%8,%9}, {%0,%1,%2,%3};"
                        : "+f"(acc[mt][nt][0]), "+f"(acc[mt][nt][1]),
                          "+f"(acc[mt][nt][2]), "+f"(acc[mt][nt][3])
                        : "r"(af[mt][0]), "r"(af[mt][1]),
                          "r"(af[mt][2]), "r"(af[mt][3]),
                          "r"(bf[nt][0]), "r"(bf[nt][1]));
        }
    }

    // epilogue: out = acc * (x_scale * w_scale) + bias ; streaming stores
    float amax = fmaxf(__uint_as_float(g_amax_bits), 1e-12f);
    float sq = 448.0f / amax;
    float total = (1.0f / sq) * __ldg(w_scale);

#pragma unroll
    for (int mt = 0; mt < 2; mt++) {
        int r0 = bm + wm * 32 + mt * 16 + (lane >> 2);
#pragma unroll
        for (int nt = 0; nt < 8; nt++) {
            int cix = bn + wn * 64 + nt * 8 + (lane & 3) * 2;
            float b0 = __ldg(&bias[cix]);
            float b1 = __ldg(&bias[cix + 1]);
            stg_cs_v2(C + (size_t)r0 * N + cix,
                      acc[mt][nt][0] * total + b0,
                      acc[mt][nt][1] * total + b1);
            stg_cs_v2(C + (size_t)(r0 + 8) * N + cix,
                      acc[mt][nt][2] * total + b0,
                      acc[mt][nt][3] * total + b1);
        }
    }
}

// ---------------------------------------------------------------------------
extern "C" void kernel_launch(void* const* d_in, const int* in_sizes, int n_in,
                              void* d_out, int out_size) {
    const float* x       = (const float*)d_in[0];
    const float* w       = (const float*)d_in[1];
    const float* w_scale = (const float*)d_in[2];
    const float* bias    = (const float*)d_in[3];
    float* out           = (float*)d_out;

    int N = in_sizes[3];
    int K = in_sizes[1] / N;
    int M = in_sizes[0] / K;
    int nx4 = (M * K) / 4;
    int nw4 = (N * K) / 4;

    cudaFuncSetAttribute(gemm_kernel,
                         cudaFuncAttributeMaxDynamicSharedMemorySize, SMEM_TOTAL);

    init_amax_kernel<<<1, 1>>>();
    amax_kernel<<<1184, 256>>>(x, nx4);                  // 8 x 148
    quantize_both_kernel<<<2368, 256>>>(x, w, nx4, nw4); // 16 x 148

    dim3 grid(N / BN, M / BM);
    gemm_kernel<<<grid, 256, SMEM_TOTAL>>>(bias, w_scale, out, M, N, K);
}